// round 14
// baseline (speedup 1.0000x reference)
#include <cuda_runtime.h>
#include <cstdint>

// SKA_Small: out[b,g,cg,h,w] = sum_{3x3 taps} x[b,g,cg,h+ki-1,w+kj-1] * w[b,g,ki*3+kj,h,w]
// x: [8,64,128,128] f32, w: [8,8,1,9,128,128] f32, out like x.
//
// R10: block = (bg, 16 rows). ALL x for the tile (18 rows incl. halos x 8 ch)
// arrives via cp.async.bulk -> smem, completing on ONE mbarrier, so compute
// never long-scoreboard-stalls on x. Halo rows at image edges are pre-zeroed
// in smem (no vertical predicates). Warp = 2 consecutive rows, all 8 channels,
// wk resident in regs (read once chip-wide), shfl horizontal halos, __stcs out.

constexpr int B = 8, C = 64, H = 128, W = 128, G = 8, CG = 8;
constexpr int HW = H * W;
constexpr int TROWS = 18;                 // 16 output rows + 2 halo rows
constexpr int ROWF = 128;                 // floats per row
constexpr int SMEM_BYTES = CG * TROWS * ROWF * 4;  // 73728

__device__ __forceinline__ uint32_t smem_u32(const void* p) {
    uint32_t a;
    asm("{ .reg .u64 t; cvta.to.shared.u64 t, %1; cvt.u32.u64 %0, t; }"
        : "=r"(a) : "l"(p));
    return a;
}

__global__ __launch_bounds__(256, 3) void ska_small_kernel(
    const float* __restrict__ x,
    const float* __restrict__ w,
    float* __restrict__ out)
{
    extern __shared__ float smx[];        // [c][18][128]
    __shared__ uint64_t mbar;

    const int t    = threadIdx.x;
    const int lane = t & 31;
    const int warp = t >> 5;              // 0..7 (= channel for staging, = row-pair for compute)
    const int bg   = blockIdx.x >> 3;     // 0..63
    const int h0   = (blockIdx.x & 7) * 16;
    const int w0   = lane * 4;

    const uint32_t mb = smem_u32(&mbar);
    if (t == 0)
        asm volatile("mbarrier.init.shared.b64 [%0], 1;" :: "r"(mb) : "memory");
    __syncthreads();

    // tile rows [first..last] map to global rows h0-1+r; clip at image edges
    const int first = (h0 == 0) ? 1 : 0;
    const int last  = (h0 == H - 16) ? TROWS - 2 : TROWS - 1;
    const int nrows = last - first + 1;

    if (t == 0)
        asm volatile("mbarrier.arrive.expect_tx.shared.b64 _, [%0], %1;"
                     :: "r"(mb), "r"((unsigned)(CG * nrows * 512)) : "memory");

    // zero the out-of-image halo row (8 ch x 128 floats = 256 float4, one per thread)
    if (h0 == 0) {
        const int c = t >> 5;
        *(float4*)(smx + (c * TROWS + 0) * ROWF + (t & 31) * 4) =
            make_float4(0.f, 0.f, 0.f, 0.f);
    }
    if (h0 == H - 16) {
        const int c = t >> 5;
        *(float4*)(smx + (c * TROWS + (TROWS - 1)) * ROWF + (t & 31) * 4) =
            make_float4(0.f, 0.f, 0.f, 0.f);
    }
    __syncthreads();   // expect_tx + zero-stores ordered before copies/compute

    // warp 'warp' stages channel c=warp: one 512B bulk copy per row
    if (lane == 0) {
        const float* src = x + ((bg * CG + warp) * H + (h0 - 1 + first)) * W;
        uint32_t dst = smem_u32(smx) + (warp * TROWS + first) * 512;
        for (int r = 0; r < nrows; r++) {
            asm volatile(
                "cp.async.bulk.shared::cta.global.mbarrier::complete_tx::bytes "
                "[%0], [%1], %2, [%3];"
                :: "r"(dst), "l"(src), "r"(512), "r"(mb) : "memory");
            src += W;
            dst += 512;
        }
    }

    // wait for all 8*nrows bulk copies
    {
        uint32_t done;
        asm volatile(
            "{\n\t.reg .pred p;\n\t"
            "mbarrier.try_wait.parity.shared.b64 p, [%1], 0;\n\t"
            "selp.b32 %0, 1, 0, p;\n\t}"
            : "=r"(done) : "r"(mb) : "memory");
        while (!done) {
            asm volatile(
                "{\n\t.reg .pred p;\n\t"
                "mbarrier.try_wait.parity.shared.b64 p, [%1], 0;\n\t"
                "selp.b32 %0, 1, 0, p;\n\t}"
                : "=r"(done) : "r"(mb) : "memory");
        }
    }

    // ---- compute: warp = rows (h0+2*warp, h0+2*warp+1), all 8 channels ----
    #pragma unroll
    for (int it = 0; it < 2; it++) {
        const int h  = h0 + warp * 2 + it;
        const int rt = warp * 2 + it + 1;           // tile row of center

        const float* wbp = w + (bg * 9) * HW + h * W + w0;
        float4 wk[9];
        #pragma unroll
        for (int k = 0; k < 9; k++)
            wk[k] = *(const float4*)(wbp + k * HW);

        float* ob = out + (bg * CG) * HW + h * W + w0;

        #pragma unroll
        for (int c = 0; c < CG; c++) {
            const float* trow = smx + (c * TROWS + rt) * ROWF + w0;

            float4 v0 = *(const float4*)(trow - ROWF);
            float4 v1 = *(const float4*)(trow);
            float4 v2 = *(const float4*)(trow + ROWF);

            float a0 = 0.f, a1 = 0.f, a2 = 0.f, a3 = 0.f;

            #pragma unroll
            for (int ki = 0; ki < 3; ki++) {
                const float4 v = (ki == 0) ? v0 : (ki == 1) ? v1 : v2;
                float l = __shfl_up_sync(0xffffffffu, v.w, 1);
                float r = __shfl_down_sync(0xffffffffu, v.x, 1);
                if (lane == 0)  l = 0.f;
                if (lane == 31) r = 0.f;

                const float4 wa = wk[ki * 3 + 0];  // tap (ki,0): x[w-1]
                const float4 wm = wk[ki * 3 + 1];  // tap (ki,1): x[w]
                const float4 wc = wk[ki * 3 + 2];  // tap (ki,2): x[w+1]

                a0 = fmaf(wa.x, l,   fmaf(wm.x, v.x, fmaf(wc.x, v.y, a0)));
                a1 = fmaf(wa.y, v.x, fmaf(wm.y, v.y, fmaf(wc.y, v.z, a1)));
                a2 = fmaf(wa.z, v.y, fmaf(wm.z, v.z, fmaf(wc.z, v.w, a2)));
                a3 = fmaf(wa.w, v.z, fmaf(wm.w, v.w, fmaf(wc.w, r,   a3)));
            }

            __stcs((float4*)(ob + c * HW), make_float4(a0, a1, a2, a3));
        }
    }
}

extern "C" void kernel_launch(void* const* d_in, const int* in_sizes, int n_in,
                              void* d_out, int out_size)
{
    const float* x = (const float*)d_in[0];
    const float* w = (const float*)d_in[1];
    float* out = (float*)d_out;

    static bool configured = false;
    if (!configured) {
        cudaFuncSetAttribute(ska_small_kernel,
                             cudaFuncAttributeMaxDynamicSharedMemorySize, SMEM_BYTES);
        configured = true;
    }

    // 64 bg x 8 row-groups = 512 blocks, 73.7KB smem each (3 blocks/SM)
    ska_small_kernel<<<512, 256, SMEM_BYTES>>>(x, w, out);
}